// round 13
// baseline (speedup 1.0000x reference)
#include <cuda_runtime.h>
#include <cuda_fp16.h>
#include <cstdint>

#define BATCH    16384
#define IN_DIM   512
#define NH       128
#define NO       256
#define NNODES   (NH + NO)         // 384
#define SRCW     (IN_DIM + NH)     // 640
#define TB       128               // batch rows per tile (4 per lane, fp16)
#define NTHREADS 1024
#define NWARPS   32
#define MAXE     16384
#define SRC_BYTES (SRCW * 256)     // 163840

// src: col-major fp16, 256B/col. (col,b) at byte col*256 + (((b>>2)^(col&31))<<3) + (b&3)*2.
// Lane l reads 8B (batches 4l..4l+3) at q ^ (l<<3), q = col*256 | ((col&31)<<3) [precomputed].
// Edge record (8B): {q, wbits}. identity: wbits = fp32 w.
//                   tanh/relu/sigmoid: wbits = half2(w, w) (sigmoid pre-halved).
// Node info (int2): w0 = e0 | d1<<13 | d2<<21 ; w1 = d3 | d4<<8 | local<<16

__device__ int2 g_edges[MAXE];
__device__ int2 g_info[NNODES];

__device__ __forceinline__ float tanha(float z) {
    float r;
    asm("tanh.approx.f32 %0, %1;" : "=f"(r) : "f"(z));
    return r;
}
__device__ __forceinline__ unsigned tanh_h2(unsigned z) {
    unsigned r;
    asm("tanh.approx.f16x2 %0, %1;" : "=r"(r) : "r"(z));
    return r;
}
__device__ __forceinline__ __half2 b2h2(unsigned b) { __half2 h; *(unsigned*)&h = b; return h; }
__device__ __forceinline__ unsigned h22b(__half2 h) { return *(unsigned*)&h; }

// ================= Fused prep: histogram + scan + scatter + LPT (1 block) =========
__global__ void __launch_bounds__(1024)
prep_all(const int* __restrict__ rows_h, const int* __restrict__ cols_h,
         const int* __restrict__ acts_h, const float* __restrict__ wh,
         const int* __restrict__ rows_o, const int* __restrict__ cols_o,
         const int* __restrict__ acts_o, const float* __restrict__ wo,
         int Eh, int Eo)
{
    __shared__ int cnt[NNODES * 4];
    __shared__ int off[NNODES * 4 + 1];
    __shared__ int wsum[32];

    const int tid = threadIdx.x, lane = tid & 31, wid = tid >> 5;

    for (int i = tid; i < NNODES * 4; i += 1024) cnt[i] = 0;
    __syncthreads();

    for (int e = tid; e < Eh; e += 1024)
        atomicAdd(&cnt[rows_h[e] * 4 + acts_h[e] - 1], 1);
    for (int e = tid; e < Eo; e += 1024)
        atomicAdd(&cnt[(NH + rows_o[e]) * 4 + acts_o[e] - 1], 1);
    __syncthreads();

    // --- parallel scan: each warp scans its 48 entries via shfl ---
    {
        const int base = wid * 48;
        const int v0 = cnt[base + lane];
        int s0 = v0;
        #pragma unroll
        for (int d = 1; d < 32; d <<= 1) {
            const int t = __shfl_up_sync(0xffffffffu, s0, d);
            if (lane >= d) s0 += t;
        }
        const int tot0 = __shfl_sync(0xffffffffu, s0, 31);
        const int v1 = (lane < 16) ? cnt[base + 32 + lane] : 0;
        int s1 = v1;
        #pragma unroll
        for (int d = 1; d < 16; d <<= 1) {
            const int t = __shfl_up_sync(0xffffffffu, s1, d);
            if (lane >= d) s1 += t;
        }
        const int tot1 = __shfl_sync(0xffffffffu, s1, 15);
        off[base + lane] = s0 - v0;
        if (lane < 16) off[base + 32 + lane] = tot0 + s1 - v1;
        if (lane == 0) wsum[wid] = tot0 + tot1;
    }
    __syncthreads();
    if (wid == 0) {
        const int v = wsum[lane];
        int ex = v;
        #pragma unroll
        for (int d = 1; d < 32; d <<= 1) {
            const int t = __shfl_up_sync(0xffffffffu, ex, d);
            if (lane >= d) ex += t;
        }
        ex -= v;
        wsum[lane] = ex;
        if (lane == 31) off[NNODES * 4] = ex + v;
    }
    __syncthreads();
    for (int i = tid; i < NNODES * 4; i += 1024) off[i] += wsum[i / 48];
    __syncthreads();

    // --- stable scatter: warp per node, ballot compaction per act ---
    for (int n = wid; n < NNODES; n += 32) {
        const bool hid = n < NH;
        const int* cols = hid ? cols_h : cols_o;
        const int* acts = hid ? acts_h : acts_o;
        const float* wp = hid ? wh : wo;
        const int sub = hid ? 0 : Eh;
        const int s = off[n * 4] - sub;
        const int e = off[(n + 1) * 4] - sub;
        int d0 = off[n * 4], d1 = off[n * 4 + 1], d2 = off[n * 4 + 2], d3 = off[n * 4 + 3];
        for (int c = s; c < e; c += 32) {
            const int idx = c + lane;
            const bool v = idx < e;
            const int act = v ? acts[idx] : 0;
            const int col = v ? cols[idx] : 0;
            const float w = v ? wp[idx] : 0.f;
            const int pk = col * 256 | ((col & 31) << 3);     // precomputed addr word
            #pragma unroll
            for (int a = 1; a <= 4; ++a) {
                const unsigned mm = __ballot_sync(0xffffffffu, act == a);
                int& d = (a == 1) ? d0 : (a == 2) ? d1 : (a == 3) ? d2 : d3;
                if (act == a) {
                    const int r = __popc(mm & ((1u << lane) - 1));
                    int wbits;
                    if (a == 1) {
                        wbits = __float_as_int(w);            // identity: fp32 w
                    } else {                                  // tanh/relu/sigmoid: half2 w
                        const float ww = (a == 4) ? 0.5f * w : w;
                        const __half2 hh = __float2half2_rn(ww);
                        wbits = *(const int*)&hh;
                    }
                    g_edges[d + r] = make_int2(pk, wbits);
                }
                d += __popc(mm);
            }
        }
    }
    __syncthreads();

    // --- LPT serpentine schedules: warp-parallel rank computation ---
    for (int n = wid; n < NNODES; n += 32) {
        const bool hid = n < NH;
        const int lo = hid ? 0 : NH, hi2 = hid ? NH : NNODES;
        const int e0 = off[n * 4], e1 = off[n * 4 + 1], e2 = off[n * 4 + 2];
        const int e3 = off[n * 4 + 3], e4 = off[(n + 1) * 4];
        const int cn = e4 - e0;
        int rank = 0;
        for (int j = lo + lane; j < hi2; j += 32) {
            const int cj = off[(j + 1) * 4] - off[j * 4];
            rank += (cj > cn) || (cj == cn && j < n);
        }
        #pragma unroll
        for (int d = 16; d; d >>= 1) rank += __shfl_down_sync(0xffffffffu, rank, d);
        if (lane == 0) {
            const int r = rank >> 5;
            int wl = rank & 31;
            if (r & 1) wl = 31 - wl;
            const int slot = (hid ? 0 : NH) + r * 32 + wl;
            const int local = hid ? n : n - NH;
            const int w0 = e0 | ((e1 - e0) << 13) | ((e2 - e1) << 21);
            const int w1 = (e3 - e2) | ((e4 - e3) << 8) | (local << 16);
            g_info[slot] = make_int2(w0, w1);
        }
    }
}

// ================= Main kernel ====================================================
__device__ __forceinline__ float4 node_accum(const char* __restrict__ srcb,
                                             const int2* __restrict__ se,
                                             int lane8,
                                             int e0, int e1, int e2, int e3, int e4)
{
    const float bias = 0.5f * (float)(e4 - e3);
    float a0 = bias, a1 = bias, a2 = bias, a3 = bias;

    // identity: fp32 w, scalar FFMA (full-precision signal path)
    #pragma unroll 4
    for (int e = e0; e < e1; ++e) {
        const int2 ed = se[e];
        const uint2 u = *(const uint2*)(srcb + (ed.x ^ lane8));
        const float w = __int_as_float(ed.y);
        const float2 f0 = __half22float2(b2h2(u.x));
        const float2 f1 = __half22float2(b2h2(u.y));
        a0 = fmaf(w, f0.x, a0); a1 = fmaf(w, f0.y, a1);
        a2 = fmaf(w, f1.x, a2); a3 = fmaf(w, f1.y, a3);
    }
    // tanh: fp16 segment accumulation (outputs bounded by 1), flush once
    {
        unsigned t01 = 0u, t23 = 0u;
        #pragma unroll 4
        for (int e = e1; e < e2; ++e) {
            const int2 ed = se[e];
            const uint2 u = *(const uint2*)(srcb + (ed.x ^ lane8));
            const __half2 wh = b2h2((unsigned)ed.y);
            t01 = h22b(__hadd2(b2h2(t01), b2h2(tanh_h2(h22b(__hmul2(wh, b2h2(u.x)))))));
            t23 = h22b(__hadd2(b2h2(t23), b2h2(tanh_h2(h22b(__hmul2(wh, b2h2(u.y)))))));
        }
        const float2 f0 = __half22float2(b2h2(t01));
        const float2 f1 = __half22float2(b2h2(t23));
        a0 += f0.x; a1 += f0.y; a2 += f1.x; a3 += f1.y;
    }
    // relu: fp16 segment accumulation, flush once
    {
        const __half2 z2 = __float2half2_rn(0.f);
        unsigned r01 = 0u, r23 = 0u;
        #pragma unroll 4
        for (int e = e2; e < e3; ++e) {
            const int2 ed = se[e];
            const uint2 u = *(const uint2*)(srcb + (ed.x ^ lane8));
            const __half2 wh = b2h2((unsigned)ed.y);
            r01 = h22b(__hadd2(b2h2(r01), __hmax2(__hmul2(wh, b2h2(u.x)), z2)));
            r23 = h22b(__hadd2(b2h2(r23), __hmax2(__hmul2(wh, b2h2(u.y)), z2)));
        }
        const float2 f0 = __half22float2(b2h2(r01));
        const float2 f1 = __half22float2(b2h2(r23));
        a0 += f0.x; a1 += f0.y; a2 += f1.x; a3 += f1.y;
    }
    // sigmoid: fp16 accumulation of tanh halves (w pre-halved), flush with x0.5
    {
        unsigned s01 = 0u, s23 = 0u;
        #pragma unroll 4
        for (int e = e3; e < e4; ++e) {
            const int2 ed = se[e];
            const uint2 u = *(const uint2*)(srcb + (ed.x ^ lane8));
            const __half2 wh = b2h2((unsigned)ed.y);
            s01 = h22b(__hadd2(b2h2(s01), b2h2(tanh_h2(h22b(__hmul2(wh, b2h2(u.x)))))));
            s23 = h22b(__hadd2(b2h2(s23), b2h2(tanh_h2(h22b(__hmul2(wh, b2h2(u.y)))))));
        }
        const float2 f0 = __half22float2(b2h2(s01));
        const float2 f1 = __half22float2(b2h2(s23));
        a0 = fmaf(0.5f, f0.x, a0); a1 = fmaf(0.5f, f0.y, a1);
        a2 = fmaf(0.5f, f1.x, a2); a3 = fmaf(0.5f, f1.y, a3);
    }
    return make_float4(a0, a1, a2, a3);
}

#define UNPACK_INFO(I)                                                       \
    const int e0 = (I).x & 8191;                                             \
    const int e1 = e0 + (((I).x >> 13) & 255);                               \
    const int e2 = e1 + (((I).x >> 21) & 255);                               \
    const int e3 = e2 + ((I).y & 255);                                       \
    const int e4 = e3 + (((I).y >> 8) & 255);                                \
    const int node = (I).y >> 16;

__global__ void __launch_bounds__(NTHREADS, 1)
wann_main(const float* __restrict__ x, float* __restrict__ out, int Etot)
{
    extern __shared__ char sm[];
    char* srcb   = sm;                                      // fp16 src tile, 160KB
    int2* se     = (int2*)(sm + SRC_BYTES);                 // [Etot] packed edges, 8B
    int2* s_info = (int2*)(sm + SRC_BYTES + ((Etot * 8 + 15) & ~15));
    unsigned* buf1 = (unsigned*)sm;                         // alias src after compute
    unsigned* buf2 = (unsigned*)(sm + NO * 33 * 4);

    const int tid = threadIdx.x, wid = tid >> 5, lane = tid & 31;
    const int lane8 = lane << 3;
    const int b0t = blockIdx.x * TB;

    // ---- stage edges + info into SMEM ----
    for (int i = tid; i < Etot; i += NTHREADS) se[i] = g_edges[i];
    if (tid < NNODES) s_info[tid] = g_info[tid];

    // ---- stage x tile: warp wid owns batch rows 4wid..4wid+3 ----
    {
        const size_t bb = (size_t)(b0t + wid * 4) * IN_DIM;
        #pragma unroll 4
        for (int k = 0; k < 16; ++k) {
            const int c = k * 32 + lane;
            const float v0 = x[bb + c];
            const float v1 = x[bb + IN_DIM + c];
            const float v2 = x[bb + 2 * IN_DIM + c];
            const float v3 = x[bb + 3 * IN_DIM + c];
            uint2 pv;
            pv.x = h22b(__floats2half2_rn(v0, v1));
            pv.y = h22b(__floats2half2_rn(v2, v3));
            *(uint2*)(srcb + c * 256 + ((wid ^ lane) << 3)) = pv;  // (c&31)==lane
        }
    }
    __syncthreads();

    // ---- hidden phase: 4 rounds, warp = node (global LPT) ----
    #pragma unroll 1
    for (int rr = 0; rr < NH / NWARPS; ++rr) {
        const int2 I = s_info[rr * NWARPS + wid];
        UNPACK_INFO(I)
        const float4 a = node_accum(srcb, se, lane8, e0, e1, e2, e3, e4);
        uint2 pv;
        pv.x = h22b(__floats2half2_rn(a.x, a.y));
        pv.y = h22b(__floats2half2_rn(a.z, a.w));
        const int hc = IN_DIM + node;
        const int qh = (hc << 8) | ((hc & 31) << 3);
        *(uint2*)(srcb + (qh ^ lane8)) = pv;
    }
    __syncthreads();

    // ---- output phase: 8 nodes per warp; results as half2 pairs (16 regs) ----
    uint2 res[NO / NWARPS];
    #pragma unroll
    for (int rr = 0; rr < NO / NWARPS; ++rr) {
        const int2 I = s_info[NH + rr * NWARPS + wid];
        UNPACK_INFO(I)
        (void)node;
        const float4 a = node_accum(srcb, se, lane8, e0, e1, e2, e3, e4);
        res[rr].x = h22b(__floats2half2_rn(tanha(a.x), tanha(a.y)));
        res[rr].y = h22b(__floats2half2_rn(tanha(a.z), tanha(a.w)));
    }

    // ---- scatter into transpose buffers (alias the now-dead src tile) ----
    __syncthreads();
    #pragma unroll
    for (int rr = 0; rr < NO / NWARPS; ++rr) {
        const int node = s_info[NH + rr * NWARPS + wid].y >> 16;
        buf1[node * 33 + lane] = res[rr].x;
        buf2[node * 33 + lane] = res[rr].y;
    }
    __syncthreads();

    // ---- coalesced write-out: warp wid handles batch rows 4wid..4wid+3 ----
    #pragma unroll
    for (int j = 0; j < 4; ++j) {
        const int b = wid * 4 + j;
        const unsigned* bp = (j & 2) ? buf2 : buf1;
        #pragma unroll
        for (int ch = 0; ch < NO / 32; ++ch) {
            const int cc = ch * 32 + lane;
            const __half2 hv = b2h2(bp[cc * 33 + wid]);
            const float f = (j & 1) ? __high2float(hv) : __low2float(hv);
            out[(size_t)(b0t + b) * NO + cc] = f;
        }
    }
}

extern "C" void kernel_launch(void* const* d_in, const int* in_sizes, int n_in,
                              void* d_out, int out_size)
{
    const float* x      = (const float*)d_in[0];
    const float* wh     = (const float*)d_in[1];
    const float* wo     = (const float*)d_in[2];
    const int*   rows_h = (const int*)d_in[3];
    const int*   cols_h = (const int*)d_in[4];
    const int*   acts_h = (const int*)d_in[5];
    const int*   rows_o = (const int*)d_in[6];
    const int*   cols_o = (const int*)d_in[7];
    const int*   acts_o = (const int*)d_in[8];
    float* out = (float*)d_out;

    const int Eh = in_sizes[1];
    const int Eo = in_sizes[2];
    const int Etot = Eh + Eo;

    prep_all<<<1, 1024>>>(rows_h, cols_h, acts_h, wh,
                          rows_o, cols_o, acts_o, wo, Eh, Eo);

    const size_t smem = (size_t)SRC_BYTES                   // fp16 src tile (bufs alias)
                      + (size_t)((Etot * 8 + 15) & ~15)     // packed 8B edges
                      + (size_t)NNODES * 8;                 // packed node info
    cudaFuncSetAttribute(wann_main, cudaFuncAttributeMaxDynamicSharedMemorySize,
                         (int)smem);
    wann_main<<<BATCH / TB, NTHREADS, smem>>>(x, out, Etot);
}

// round 16
// speedup vs baseline: 1.1775x; 1.1775x over previous
#include <cuda_runtime.h>
#include <cuda_fp16.h>
#include <cstdint>

#define BATCH    16384
#define IN_DIM   512
#define NH       128
#define NO       256
#define NNODES   (NH + NO)         // 384
#define SRCW     (IN_DIM + NH)     // 640
#define TB       128               // batch rows per tile (4 per lane, fp16)
#define NTHREADS 1024
#define NWARPS   32
#define MAXE     16384
#define SRC_BYTES (SRCW * 256)     // 163840

// src: col-major fp16, 256B/col. (col,b) at byte col*256 + (((b>>2)^(col&31))<<3) + (b&3)*2.
// Lane l reads 8B (batches 4l..4l+3) at q ^ (l<<3), q = col*256 | ((col&31)<<3) [precomputed].
// Edge record (8B): {q, wbits}. identity: wbits = fp32 w.
//                   tanh/relu/sigmoid: wbits = half2(w, w) (sigmoid pre-halved).
// Node info (int2): w0 = e0 | d1<<13 | d2<<21 ; w1 = d3 | d4<<8 | local<<16

__device__ int2 g_edges[MAXE];
__device__ int2 g_info[NNODES];

__device__ __forceinline__ float tanha(float z) {
    float r;
    asm("tanh.approx.f32 %0, %1;" : "=f"(r) : "f"(z));
    return r;
}
__device__ __forceinline__ unsigned tanh_h2(unsigned z) {
    unsigned r;
    asm("tanh.approx.f16x2 %0, %1;" : "=r"(r) : "r"(z));
    return r;
}
__device__ __forceinline__ __half2 b2h2(unsigned b) { __half2 h; *(unsigned*)&h = b; return h; }
__device__ __forceinline__ unsigned h22b(__half2 h) { return *(unsigned*)&h; }

// ================= Fused prep (R12 version — measured-fast) =======================
__global__ void __launch_bounds__(1024)
prep_all(const int* __restrict__ rows_h, const int* __restrict__ cols_h,
         const int* __restrict__ acts_h, const float* __restrict__ wh,
         const int* __restrict__ rows_o, const int* __restrict__ cols_o,
         const int* __restrict__ acts_o, const float* __restrict__ wo,
         int Eh, int Eo)
{
    __shared__ int cnt[NNODES * 4];
    __shared__ int off[NNODES * 4 + 1];
    __shared__ int wsum[32];

    const int tid = threadIdx.x, lane = tid & 31, wid = tid >> 5;

    for (int i = tid; i < NNODES * 4; i += 1024) cnt[i] = 0;
    __syncthreads();

    for (int e = tid; e < Eh; e += 1024)
        atomicAdd(&cnt[rows_h[e] * 4 + acts_h[e] - 1], 1);
    for (int e = tid; e < Eo; e += 1024)
        atomicAdd(&cnt[(NH + rows_o[e]) * 4 + acts_o[e] - 1], 1);
    __syncthreads();

    if (lane == 0) {
        const int base = wid * 48;
        int run = 0;
        for (int i = 0; i < 48; ++i) { off[base + i] = run; run += cnt[base + i]; }
        wsum[wid] = run;
    }
    __syncthreads();
    if (wid == 0) {
        const int v = wsum[lane];
        int ex = v;
        #pragma unroll
        for (int d = 1; d < 32; d <<= 1) {
            const int t = __shfl_up_sync(0xffffffffu, ex, d);
            if (lane >= d) ex += t;
        }
        ex -= v;
        wsum[lane] = ex;
        if (lane == 31) off[NNODES * 4] = ex + v;
    }
    __syncthreads();
    for (int i = tid; i < NNODES * 4; i += 1024) off[i] += wsum[i / 48];
    __syncthreads();

    // stable scatter: warp per node, ballot compaction per act
    for (int n = wid; n < NNODES; n += 32) {
        const bool hid = n < NH;
        const int* cols = hid ? cols_h : cols_o;
        const int* acts = hid ? acts_h : acts_o;
        const float* wp = hid ? wh : wo;
        const int sub = hid ? 0 : Eh;
        const int s = off[n * 4] - sub;
        const int e = off[(n + 1) * 4] - sub;
        int d0 = off[n * 4], d1 = off[n * 4 + 1], d2 = off[n * 4 + 2], d3 = off[n * 4 + 3];
        for (int c = s; c < e; c += 32) {
            const int idx = c + lane;
            const bool v = idx < e;
            const int act = v ? acts[idx] : 0;
            const int col = v ? cols[idx] : 0;
            const float w = v ? wp[idx] : 0.f;
            const int pk = col * 256 | ((col & 31) << 3);     // precomputed addr word
            #pragma unroll
            for (int a = 1; a <= 4; ++a) {
                const unsigned mm = __ballot_sync(0xffffffffu, act == a);
                int& d = (a == 1) ? d0 : (a == 2) ? d1 : (a == 3) ? d2 : d3;
                if (act == a) {
                    const int r = __popc(mm & ((1u << lane) - 1));
                    int wbits;
                    if (a == 1) {
                        wbits = __float_as_int(w);            // identity: fp32 w
                    } else {                                  // tanh/relu/sigmoid: half2 w
                        const float ww = (a == 4) ? 0.5f * w : w;
                        const __half2 hh = __float2half2_rn(ww);
                        wbits = *(const int*)&hh;
                    }
                    g_edges[d + r] = make_int2(pk, wbits);
                }
                d += __popc(mm);
            }
        }
    }
    __syncthreads();

    // LPT serpentine schedules: hidden over 128, output over all 256. Packed info.
    if (tid < NNODES) {
        const int n = tid;
        const int e0 = off[n * 4], e1 = off[n * 4 + 1], e2 = off[n * 4 + 2];
        const int e3 = off[n * 4 + 3], e4 = off[(n + 1) * 4];
        const int cn = e4 - e0;
        int slot, local;
        if (n < NH) {
            int rank = 0;
            for (int j = 0; j < NH; ++j) {
                const int cj = off[(j + 1) * 4] - off[j * 4];
                rank += (cj > cn) || (cj == cn && j < n);
            }
            const int r = rank >> 5;
            int wl = rank & 31;
            if (r & 1) wl = 31 - wl;
            slot = r * 32 + wl;
            local = n;
        } else {
            int rank = 0;
            for (int j = NH; j < NNODES; ++j) {
                const int cj = off[(j + 1) * 4] - off[j * 4];
                rank += (cj > cn) || (cj == cn && j < n);
            }
            const int r = rank >> 5;
            int wl = rank & 31;
            if (r & 1) wl = 31 - wl;
            slot = NH + r * 32 + wl;
            local = n - NH;
        }
        const int w0 = e0 | ((e1 - e0) << 13) | ((e2 - e1) << 21);
        const int w1 = (e3 - e2) | ((e4 - e3) << 8) | (local << 16);
        g_info[slot] = make_int2(w0, w1);
    }
}

// ================= Main kernel (R13 version) ======================================
__device__ __forceinline__ float4 node_accum(const char* __restrict__ srcb,
                                             const int2* __restrict__ se,
                                             int lane8,
                                             int e0, int e1, int e2, int e3, int e4)
{
    const float bias = 0.5f * (float)(e4 - e3);
    float a0 = bias, a1 = bias, a2 = bias, a3 = bias;

    // identity: fp32 w, scalar FFMA (full-precision signal path)
    #pragma unroll 4
    for (int e = e0; e < e1; ++e) {
        const int2 ed = se[e];
        const uint2 u = *(const uint2*)(srcb + (ed.x ^ lane8));
        const float w = __int_as_float(ed.y);
        const float2 f0 = __half22float2(b2h2(u.x));
        const float2 f1 = __half22float2(b2h2(u.y));
        a0 = fmaf(w, f0.x, a0); a1 = fmaf(w, f0.y, a1);
        a2 = fmaf(w, f1.x, a2); a3 = fmaf(w, f1.y, a3);
    }
    // tanh: fp16 segment accumulation (outputs bounded), flush once
    {
        unsigned t01 = 0u, t23 = 0u;
        #pragma unroll 4
        for (int e = e1; e < e2; ++e) {
            const int2 ed = se[e];
            const uint2 u = *(const uint2*)(srcb + (ed.x ^ lane8));
            const __half2 wh = b2h2((unsigned)ed.y);
            t01 = h22b(__hadd2(b2h2(t01), b2h2(tanh_h2(h22b(__hmul2(wh, b2h2(u.x)))))));
            t23 = h22b(__hadd2(b2h2(t23), b2h2(tanh_h2(h22b(__hmul2(wh, b2h2(u.y)))))));
        }
        const float2 f0 = __half22float2(b2h2(t01));
        const float2 f1 = __half22float2(b2h2(t23));
        a0 += f0.x; a1 += f0.y; a2 += f1.x; a3 += f1.y;
    }
    // relu: fp16 segment accumulation, flush once
    {
        const __half2 z2 = __float2half2_rn(0.f);
        unsigned r01 = 0u, r23 = 0u;
        #pragma unroll 4
        for (int e = e2; e < e3; ++e) {
            const int2 ed = se[e];
            const uint2 u = *(const uint2*)(srcb + (ed.x ^ lane8));
            const __half2 wh = b2h2((unsigned)ed.y);
            r01 = h22b(__hadd2(b2h2(r01), __hmax2(__hmul2(wh, b2h2(u.x)), z2)));
            r23 = h22b(__hadd2(b2h2(r23), __hmax2(__hmul2(wh, b2h2(u.y)), z2)));
        }
        const float2 f0 = __half22float2(b2h2(r01));
        const float2 f1 = __half22float2(b2h2(r23));
        a0 += f0.x; a1 += f0.y; a2 += f1.x; a3 += f1.y;
    }
    // sigmoid: fp16 accumulation of tanh halves (w pre-halved), flush with x0.5
    {
        unsigned s01 = 0u, s23 = 0u;
        #pragma unroll 4
        for (int e = e3; e < e4; ++e) {
            const int2 ed = se[e];
            const uint2 u = *(const uint2*)(srcb + (ed.x ^ lane8));
            const __half2 wh = b2h2((unsigned)ed.y);
            s01 = h22b(__hadd2(b2h2(s01), b2h2(tanh_h2(h22b(__hmul2(wh, b2h2(u.x)))))));
            s23 = h22b(__hadd2(b2h2(s23), b2h2(tanh_h2(h22b(__hmul2(wh, b2h2(u.y)))))));
        }
        const float2 f0 = __half22float2(b2h2(s01));
        const float2 f1 = __half22float2(b2h2(s23));
        a0 = fmaf(0.5f, f0.x, a0); a1 = fmaf(0.5f, f0.y, a1);
        a2 = fmaf(0.5f, f1.x, a2); a3 = fmaf(0.5f, f1.y, a3);
    }
    return make_float4(a0, a1, a2, a3);
}

#define UNPACK_INFO(I)                                                       \
    const int e0 = (I).x & 8191;                                             \
    const int e1 = e0 + (((I).x >> 13) & 255);                               \
    const int e2 = e1 + (((I).x >> 21) & 255);                               \
    const int e3 = e2 + ((I).y & 255);                                       \
    const int e4 = e3 + (((I).y >> 8) & 255);                                \
    const int node = (I).y >> 16;

__global__ void __launch_bounds__(NTHREADS, 1)
wann_main(const float* __restrict__ x, float* __restrict__ out, int Etot)
{
    extern __shared__ char sm[];
    char* srcb   = sm;                                      // fp16 src tile, 160KB
    int2* se     = (int2*)(sm + SRC_BYTES);                 // [Etot] packed edges, 8B
    int2* s_info = (int2*)(sm + SRC_BYTES + ((Etot * 8 + 15) & ~15));
    unsigned* buf1 = (unsigned*)sm;                         // alias src after compute
    unsigned* buf2 = (unsigned*)(sm + NO * 33 * 4);

    const int tid = threadIdx.x, wid = tid >> 5, lane = tid & 31;
    const int lane8 = lane << 3;
    const int b0t = blockIdx.x * TB;

    // ---- stage edges (int4 = 2 edges per load) + info into SMEM ----
    {
        const int n4 = Etot >> 1;                           // int4 count
        const int4* gsrc = (const int4*)g_edges;
        int4* sdst = (int4*)se;
        for (int i = tid; i < n4; i += NTHREADS) sdst[i] = gsrc[i];
        if ((Etot & 1) && tid == 0) se[Etot - 1] = g_edges[Etot - 1];
    }
    if (tid < NNODES) s_info[tid] = g_info[tid];

    // ---- stage x tile: warp wid owns batch rows 4wid..4wid+3 ----
    {
        const size_t bb = (size_t)(b0t + wid * 4) * IN_DIM;
        #pragma unroll 4
        for (int k = 0; k < 16; ++k) {
            const int c = k * 32 + lane;
            const float v0 = x[bb + c];
            const float v1 = x[bb + IN_DIM + c];
            const float v2 = x[bb + 2 * IN_DIM + c];
            const float v3 = x[bb + 3 * IN_DIM + c];
            uint2 pv;
            pv.x = h22b(__floats2half2_rn(v0, v1));
            pv.y = h22b(__floats2half2_rn(v2, v3));
            *(uint2*)(srcb + c * 256 + ((wid ^ lane) << 3)) = pv;  // (c&31)==lane
        }
    }
    __syncthreads();

    // ---- hidden phase: 4 rounds, warp = node (global LPT) ----
    #pragma unroll 1
    for (int rr = 0; rr < NH / NWARPS; ++rr) {
        const int2 I = s_info[rr * NWARPS + wid];
        UNPACK_INFO(I)
        const float4 a = node_accum(srcb, se, lane8, e0, e1, e2, e3, e4);
        uint2 pv;
        pv.x = h22b(__floats2half2_rn(a.x, a.y));
        pv.y = h22b(__floats2half2_rn(a.z, a.w));
        const int hc = IN_DIM + node;
        const int qh = (hc << 8) | ((hc & 31) << 3);
        *(uint2*)(srcb + (qh ^ lane8)) = pv;
    }
    __syncthreads();

    // ---- output phase: 8 nodes per warp; results as half2 pairs (16 regs) ----
    uint2 res[NO / NWARPS];
    #pragma unroll
    for (int rr = 0; rr < NO / NWARPS; ++rr) {
        const int2 I = s_info[NH + rr * NWARPS + wid];
        UNPACK_INFO(I)
        (void)node;
        const float4 a = node_accum(srcb, se, lane8, e0, e1, e2, e3, e4);
        res[rr].x = h22b(__floats2half2_rn(tanha(a.x), tanha(a.y)));
        res[rr].y = h22b(__floats2half2_rn(tanha(a.z), tanha(a.w)));
    }

    // ---- scatter into transpose buffers (alias the now-dead src tile) ----
    __syncthreads();
    #pragma unroll
    for (int rr = 0; rr < NO / NWARPS; ++rr) {
        const int node = s_info[NH + rr * NWARPS + wid].y >> 16;
        buf1[node * 33 + lane] = res[rr].x;
        buf2[node * 33 + lane] = res[rr].y;
    }
    __syncthreads();

    // ---- coalesced write-out: warp wid handles batch rows 4wid..4wid+3 ----
    #pragma unroll
    for (int j = 0; j < 4; ++j) {
        const int b = wid * 4 + j;
        const unsigned* bp = (j & 2) ? buf2 : buf1;
        #pragma unroll
        for (int ch = 0; ch < NO / 32; ++ch) {
            const int cc = ch * 32 + lane;
            const __half2 hv = b2h2(bp[cc * 33 + wid]);
            const float f = (j & 1) ? __high2float(hv) : __low2float(hv);
            out[(size_t)(b0t + b) * NO + cc] = f;
        }
    }
}

extern "C" void kernel_launch(void* const* d_in, const int* in_sizes, int n_in,
                              void* d_out, int out_size)
{
    const float* x      = (const float*)d_in[0];
    const float* wh     = (const float*)d_in[1];
    const float* wo     = (const float*)d_in[2];
    const int*   rows_h = (const int*)d_in[3];
    const int*   cols_h = (const int*)d_in[4];
    const int*   acts_h = (const int*)d_in[5];
    const int*   rows_o = (const int*)d_in[6];
    const int*   cols_o = (const int*)d_in[7];
    const int*   acts_o = (const int*)d_in[8];
    float* out = (float*)d_out;

    const int Eh = in_sizes[1];
    const int Eo = in_sizes[2];
    const int Etot = Eh + Eo;

    prep_all<<<1, 1024>>>(rows_h, cols_h, acts_h, wh,
                          rows_o, cols_o, acts_o, wo, Eh, Eo);

    const size_t smem = (size_t)SRC_BYTES                   // fp16 src tile (bufs alias)
                      + (size_t)((Etot * 8 + 15) & ~15)     // packed 8B edges
                      + (size_t)NNODES * 8;                 // packed node info
    cudaFuncSetAttribute(wann_main, cudaFuncAttributeMaxDynamicSharedMemorySize,
                         (int)smem);
    wann_main<<<BATCH / TB, NTHREADS, smem>>>(x, out, Etot);
}

// round 17
// speedup vs baseline: 1.2296x; 1.0442x over previous
#include <cuda_runtime.h>
#include <cuda_fp16.h>
#include <cstdint>

#define BATCH    16384
#define IN_DIM   512
#define NH       128
#define NO       256
#define NNODES   (NH + NO)         // 384
#define SRCW     (IN_DIM + NH)     // 640
#define TB       128               // batch rows per tile (4 per lane, fp16)
#define NTHREADS 1024
#define NWARPS   32
#define SRC_BYTES (SRCW * 256)     // 163840

// src: col-major fp16, 256B/col. (col,b) at byte col*256 + (((b>>2)^(col&31))<<3) + (b&3)*2.
// Lane l reads 8B (batches 4l..4l+3) at q ^ (l<<3), q = col*256 | ((col&31)<<3) [precomputed].
// Edge record (8B): {q, wbits}. identity: wbits = fp32 w.
//                   tanh/relu/sigmoid: wbits = half2(w, w) (sigmoid pre-halved).
// Node info (int2): w0 = e0 | d1<<13 | d2<<21 ; w1 = d3 | d4<<8 | local<<16
//
// Prep (histogram/scan/scatter/LPT) is fused into the main kernel: every block
// rebuilds the edge table in its own SMEM. cnt/off/wsum live in the src tile
// region (x is staged AFTER prep completes), se/s_info in their own regions.

__device__ __forceinline__ float tanha(float z) {
    float r;
    asm("tanh.approx.f32 %0, %1;" : "=f"(r) : "f"(z));
    return r;
}
__device__ __forceinline__ unsigned tanh_h2(unsigned z) {
    unsigned r;
    asm("tanh.approx.f16x2 %0, %1;" : "=r"(r) : "r"(z));
    return r;
}
__device__ __forceinline__ __half2 b2h2(unsigned b) { __half2 h; *(unsigned*)&h = b; return h; }
__device__ __forceinline__ unsigned h22b(__half2 h) { return *(unsigned*)&h; }

// ================= Hot per-node accumulator (unchanged from R13/R16) ==============
__device__ __forceinline__ float4 node_accum(const char* __restrict__ srcb,
                                             const int2* __restrict__ se,
                                             int lane8,
                                             int e0, int e1, int e2, int e3, int e4)
{
    const float bias = 0.5f * (float)(e4 - e3);
    float a0 = bias, a1 = bias, a2 = bias, a3 = bias;

    // identity: fp32 w, scalar FFMA (full-precision signal path)
    #pragma unroll 4
    for (int e = e0; e < e1; ++e) {
        const int2 ed = se[e];
        const uint2 u = *(const uint2*)(srcb + (ed.x ^ lane8));
        const float w = __int_as_float(ed.y);
        const float2 f0 = __half22float2(b2h2(u.x));
        const float2 f1 = __half22float2(b2h2(u.y));
        a0 = fmaf(w, f0.x, a0); a1 = fmaf(w, f0.y, a1);
        a2 = fmaf(w, f1.x, a2); a3 = fmaf(w, f1.y, a3);
    }
    // tanh: fp16 segment accumulation (bounded outputs), flush once
    {
        unsigned t01 = 0u, t23 = 0u;
        #pragma unroll 4
        for (int e = e1; e < e2; ++e) {
            const int2 ed = se[e];
            const uint2 u = *(const uint2*)(srcb + (ed.x ^ lane8));
            const __half2 wh = b2h2((unsigned)ed.y);
            t01 = h22b(__hadd2(b2h2(t01), b2h2(tanh_h2(h22b(__hmul2(wh, b2h2(u.x)))))));
            t23 = h22b(__hadd2(b2h2(t23), b2h2(tanh_h2(h22b(__hmul2(wh, b2h2(u.y)))))));
        }
        const float2 f0 = __half22float2(b2h2(t01));
        const float2 f1 = __half22float2(b2h2(t23));
        a0 += f0.x; a1 += f0.y; a2 += f1.x; a3 += f1.y;
    }
    // relu: fp16 segment accumulation, flush once
    {
        const __half2 z2 = __float2half2_rn(0.f);
        unsigned r01 = 0u, r23 = 0u;
        #pragma unroll 4
        for (int e = e2; e < e3; ++e) {
            const int2 ed = se[e];
            const uint2 u = *(const uint2*)(srcb + (ed.x ^ lane8));
            const __half2 wh = b2h2((unsigned)ed.y);
            r01 = h22b(__hadd2(b2h2(r01), __hmax2(__hmul2(wh, b2h2(u.x)), z2)));
            r23 = h22b(__hadd2(b2h2(r23), __hmax2(__hmul2(wh, b2h2(u.y)), z2)));
        }
        const float2 f0 = __half22float2(b2h2(r01));
        const float2 f1 = __half22float2(b2h2(r23));
        a0 += f0.x; a1 += f0.y; a2 += f1.x; a3 += f1.y;
    }
    // sigmoid: fp16 accumulation of tanh halves (w pre-halved), flush with x0.5
    {
        unsigned s01 = 0u, s23 = 0u;
        #pragma unroll 4
        for (int e = e3; e < e4; ++e) {
            const int2 ed = se[e];
            const uint2 u = *(const uint2*)(srcb + (ed.x ^ lane8));
            const __half2 wh = b2h2((unsigned)ed.y);
            s01 = h22b(__hadd2(b2h2(s01), b2h2(tanh_h2(h22b(__hmul2(wh, b2h2(u.x)))))));
            s23 = h22b(__hadd2(b2h2(s23), b2h2(tanh_h2(h22b(__hmul2(wh, b2h2(u.y)))))));
        }
        const float2 f0 = __half22float2(b2h2(s01));
        const float2 f1 = __half22float2(b2h2(s23));
        a0 = fmaf(0.5f, f0.x, a0); a1 = fmaf(0.5f, f0.y, a1);
        a2 = fmaf(0.5f, f1.x, a2); a3 = fmaf(0.5f, f1.y, a3);
    }
    return make_float4(a0, a1, a2, a3);
}

#define UNPACK_INFO(I)                                                       \
    const int e0 = (I).x & 8191;                                             \
    const int e1 = e0 + (((I).x >> 13) & 255);                               \
    const int e2 = e1 + (((I).x >> 21) & 255);                               \
    const int e3 = e2 + ((I).y & 255);                                       \
    const int e4 = e3 + (((I).y >> 8) & 255);                                \
    const int node = (I).y >> 16;

__global__ void __launch_bounds__(NTHREADS, 1)
wann_main(const float* __restrict__ x,
          const int* __restrict__ rows_h, const int* __restrict__ cols_h,
          const int* __restrict__ acts_h, const float* __restrict__ wh,
          const int* __restrict__ rows_o, const int* __restrict__ cols_o,
          const int* __restrict__ acts_o, const float* __restrict__ wo,
          float* __restrict__ out, int Eh, int Eo)
{
    extern __shared__ char sm[];
    char* srcb   = sm;                                      // fp16 src tile, 160KB
    const int Etot = Eh + Eo;
    int2* se     = (int2*)(sm + SRC_BYTES);                 // [Etot] packed edges, 8B
    int2* s_info = (int2*)(sm + SRC_BYTES + ((Etot * 8 + 15) & ~15));
    unsigned* buf1 = (unsigned*)sm;                         // alias src after compute
    unsigned* buf2 = (unsigned*)(sm + NO * 33 * 4);
    // Prep scratch lives in the src tile region (x staged after prep)
    int* cnt  = (int*)sm;                                   // [NNODES*4]
    int* off  = cnt + NNODES * 4;                           // [NNODES*4+1]
    int* wsum = off + NNODES * 4 + 1;                       // [32]

    const int tid = threadIdx.x, wid = tid >> 5, lane = tid & 31;
    const int lane8 = lane << 3;
    const int b0t = blockIdx.x * TB;

    // ================= In-block prep: histogram + scan + scatter + LPT ===========
    for (int i = tid; i < NNODES * 4; i += NTHREADS) cnt[i] = 0;
    __syncthreads();

    for (int e = tid; e < Eh; e += NTHREADS)
        atomicAdd(&cnt[rows_h[e] * 4 + acts_h[e] - 1], 1);
    for (int e = tid; e < Eo; e += NTHREADS)
        atomicAdd(&cnt[(NH + rows_o[e]) * 4 + acts_o[e] - 1], 1);
    __syncthreads();

    if (lane == 0) {                                        // per-warp serial scan (48)
        const int base = wid * 48;
        int run = 0;
        for (int i = 0; i < 48; ++i) { off[base + i] = run; run += cnt[base + i]; }
        wsum[wid] = run;
    }
    __syncthreads();
    if (wid == 0) {                                         // warp scan of block sums
        const int v = wsum[lane];
        int ex = v;
        #pragma unroll
        for (int d = 1; d < 32; d <<= 1) {
            const int t = __shfl_up_sync(0xffffffffu, ex, d);
            if (lane >= d) ex += t;
        }
        ex -= v;
        wsum[lane] = ex;
        if (lane == 31) off[NNODES * 4] = ex + v;
    }
    __syncthreads();
    for (int i = tid; i < NNODES * 4; i += NTHREADS) off[i] += wsum[i / 48];
    __syncthreads();

    // stable scatter: warp per node, ballot compaction per act -> SMEM se
    for (int n = wid; n < NNODES; n += 32) {
        const bool hid = n < NH;
        const int* cols = hid ? cols_h : cols_o;
        const int* acts = hid ? acts_h : acts_o;
        const float* wp = hid ? wh : wo;
        const int sub = hid ? 0 : Eh;
        const int s = off[n * 4] - sub;
        const int e = off[(n + 1) * 4] - sub;
        int d0 = off[n * 4], d1 = off[n * 4 + 1], d2 = off[n * 4 + 2], d3 = off[n * 4 + 3];
        for (int c = s; c < e; c += 32) {
            const int idx = c + lane;
            const bool v = idx < e;
            const int act = v ? acts[idx] : 0;
            const int col = v ? cols[idx] : 0;
            const float w = v ? wp[idx] : 0.f;
            const int pk = col * 256 | ((col & 31) << 3);   // precomputed addr word
            #pragma unroll
            for (int a = 1; a <= 4; ++a) {
                const unsigned mm = __ballot_sync(0xffffffffu, act == a);
                int& d = (a == 1) ? d0 : (a == 2) ? d1 : (a == 3) ? d2 : d3;
                if (act == a) {
                    const int r = __popc(mm & ((1u << lane) - 1));
                    int wbits;
                    if (a == 1) {
                        wbits = __float_as_int(w);          // identity: fp32 w
                    } else {                                // tanh/relu/sigmoid: half2 w
                        const float ww = (a == 4) ? 0.5f * w : w;
                        const __half2 hh = __float2half2_rn(ww);
                        wbits = *(const int*)&hh;
                    }
                    se[d + r] = make_int2(pk, wbits);
                }
                d += __popc(mm);
            }
        }
    }
    __syncthreads();

    // LPT serpentine schedules + packed per-slot node info -> SMEM s_info
    if (tid < NNODES) {
        const int n = tid;
        const int e0 = off[n * 4], e1 = off[n * 4 + 1], e2 = off[n * 4 + 2];
        const int e3 = off[n * 4 + 3], e4 = off[(n + 1) * 4];
        const int cn = e4 - e0;
        int slot, local;
        if (n < NH) {
            int rank = 0;
            for (int j = 0; j < NH; ++j) {
                const int cj = off[(j + 1) * 4] - off[j * 4];
                rank += (cj > cn) || (cj == cn && j < n);
            }
            const int r = rank >> 5;
            int wl = rank & 31;
            if (r & 1) wl = 31 - wl;
            slot = r * 32 + wl;
            local = n;
        } else {
            int rank = 0;
            for (int j = NH; j < NNODES; ++j) {
                const int cj = off[(j + 1) * 4] - off[j * 4];
                rank += (cj > cn) || (cj == cn && j < n);
            }
            const int r = rank >> 5;
            int wl = rank & 31;
            if (r & 1) wl = 31 - wl;
            slot = NH + r * 32 + wl;
            local = n - NH;
        }
        const int w0 = e0 | ((e1 - e0) << 13) | ((e2 - e1) << 21);
        const int w1 = (e3 - e2) | ((e4 - e3) << 8) | (local << 16);
        s_info[slot] = make_int2(w0, w1);
    }
    __syncthreads();                                        // prep done; src region free

    // ================= Stage x tile: warp wid owns batch rows 4wid..4wid+3 =======
    {
        const size_t bb = (size_t)(b0t + wid * 4) * IN_DIM;
        #pragma unroll 4
        for (int k = 0; k < 16; ++k) {
            const int c = k * 32 + lane;
            const float v0 = x[bb + c];
            const float v1 = x[bb + IN_DIM + c];
            const float v2 = x[bb + 2 * IN_DIM + c];
            const float v3 = x[bb + 3 * IN_DIM + c];
            uint2 pv;
            pv.x = h22b(__floats2half2_rn(v0, v1));
            pv.y = h22b(__floats2half2_rn(v2, v3));
            *(uint2*)(srcb + c * 256 + ((wid ^ lane) << 3)) = pv;  // (c&31)==lane
        }
    }
    __syncthreads();

    // ================= Hidden phase: 4 rounds, warp = node (global LPT) ==========
    #pragma unroll 1
    for (int rr = 0; rr < NH / NWARPS; ++rr) {
        const int2 I = s_info[rr * NWARPS + wid];
        UNPACK_INFO(I)
        const float4 a = node_accum(srcb, se, lane8, e0, e1, e2, e3, e4);
        uint2 pv;
        pv.x = h22b(__floats2half2_rn(a.x, a.y));
        pv.y = h22b(__floats2half2_rn(a.z, a.w));
        const int hc = IN_DIM + node;
        const int qh = (hc << 8) | ((hc & 31) << 3);
        *(uint2*)(srcb + (qh ^ lane8)) = pv;
    }
    __syncthreads();

    // ================= Output phase: 8 nodes per warp; half2 results =============
    uint2 res[NO / NWARPS];
    #pragma unroll
    for (int rr = 0; rr < NO / NWARPS; ++rr) {
        const int2 I = s_info[NH + rr * NWARPS + wid];
        UNPACK_INFO(I)
        (void)node;
        const float4 a = node_accum(srcb, se, lane8, e0, e1, e2, e3, e4);
        res[rr].x = h22b(__floats2half2_rn(tanha(a.x), tanha(a.y)));
        res[rr].y = h22b(__floats2half2_rn(tanha(a.z), tanha(a.w)));
    }

    // ---- scatter into transpose buffers (alias the now-dead src tile) ----
    __syncthreads();
    #pragma unroll
    for (int rr = 0; rr < NO / NWARPS; ++rr) {
        const int node = s_info[NH + rr * NWARPS + wid].y >> 16;
        buf1[node * 33 + lane] = res[rr].x;
        buf2[node * 33 + lane] = res[rr].y;
    }
    __syncthreads();

    // ---- coalesced write-out: warp wid handles batch rows 4wid..4wid+3 ----
    #pragma unroll
    for (int j = 0; j < 4; ++j) {
        const int b = wid * 4 + j;
        const unsigned* bp = (j & 2) ? buf2 : buf1;
        #pragma unroll
        for (int ch = 0; ch < NO / 32; ++ch) {
            const int cc = ch * 32 + lane;
            const __half2 hv = b2h2(bp[cc * 33 + wid]);
            const float f = (j & 1) ? __high2float(hv) : __low2float(hv);
            out[(size_t)(b0t + b) * NO + cc] = f;
        }
    }
}

extern "C" void kernel_launch(void* const* d_in, const int* in_sizes, int n_in,
                              void* d_out, int out_size)
{
    const float* x      = (const float*)d_in[0];
    const float* wh     = (const float*)d_in[1];
    const float* wo     = (const float*)d_in[2];
    const int*   rows_h = (const int*)d_in[3];
    const int*   cols_h = (const int*)d_in[4];
    const int*   acts_h = (const int*)d_in[5];
    const int*   rows_o = (const int*)d_in[6];
    const int*   cols_o = (const int*)d_in[7];
    const int*   acts_o = (const int*)d_in[8];
    float* out = (float*)d_out;

    const int Eh = in_sizes[1];
    const int Eo = in_sizes[2];
    const int Etot = Eh + Eo;

    const size_t smem = (size_t)SRC_BYTES                   // fp16 src tile (+prep scratch/bufs alias)
                      + (size_t)((Etot * 8 + 15) & ~15)     // packed 8B edges
                      + (size_t)NNODES * 8;                 // packed node info
    cudaFuncSetAttribute(wann_main, cudaFuncAttributeMaxDynamicSharedMemorySize,
                         (int)smem);
    wann_main<<<BATCH / TB, NTHREADS, smem>>>(x, rows_h, cols_h, acts_h, wh,
                                              rows_o, cols_o, acts_o, wo,
                                              out, Eh, Eo);
}